// round 9
// baseline (speedup 1.0000x reference)
#include <cuda_runtime.h>

// Shapes (fixed by the problem)
#define B_  32
#define C_  256
#define HW4 784                        // (56*56)/4 float4 per plane

// Consumer table, built by leader block:
// g_cons[t][c] describes who consumes source plane (tensor t, channel c):
//   bit0        : keep  -> output (feature t, channel c)
//   bit10       : cross -> output (feature 1-t, channel xc)
//   bits[1..9]  : xc
// Persists across graph replays; leader rewrites identical values each call.
__device__ int g_cons[2][C_];
__device__ int g_flag;

// ---------------------------------------------------------------------------
// Single kernel. Block 0: build map + consumer table. Blocks 1..2*C*B:
// source-centric copy — read one source plane once (streaming loads),
// write to 1-2 output planes (default-policy stores buffer in L2).
// ---------------------------------------------------------------------------
__global__ __launch_bounds__(256, 8)
void exchange_fused(const float* __restrict__ w1,
                    const float* __restrict__ w2,
                    const float* __restrict__ thr_p,
                    const float4* __restrict__ x1,
                    const float4* __restrict__ x2,
                    float4* __restrict__ out) {
    const int tid = threadIdx.x;

    if (blockIdx.x == 0) {
        // ---------------- leader: build consumer table ----------------
        __shared__ float a[2][C_];
        __shared__ int   order[2][C_];
        __shared__ int   warpcnt[2][8];
        __shared__ int   cross[2][C_];   // cross[t][c] = (xc|512) or 0

        const int c = tid;
        const float thr = thr_p[0];
        const float v1 = fabsf(w1[c]);
        const float v2 = fabsf(w2[c]);
        a[0][c] = v1;
        a[1][c] = v2;
        cross[0][c] = 0;
        cross[1][c] = 0;
        __syncthreads();

        // Stable descending rank (ties by ascending index), float4 smem reads
        int r1 = 0, r2 = 0;
        const float4* a1v = (const float4*)a[0];
        const float4* a2v = (const float4*)a[1];
#pragma unroll 4
        for (int j4 = 0; j4 < C_ / 4; j4++) {
            const float4 q1 = a1v[j4];
            const float4 q2 = a2v[j4];
            const int j = j4 * 4;
            r1 += (q1.x > v1) || (q1.x == v1 && (j + 0) < c);
            r1 += (q1.y > v1) || (q1.y == v1 && (j + 1) < c);
            r1 += (q1.z > v1) || (q1.z == v1 && (j + 2) < c);
            r1 += (q1.w > v1) || (q1.w == v1 && (j + 3) < c);
            r2 += (q2.x > v2) || (q2.x == v2 && (j + 0) < c);
            r2 += (q2.y > v2) || (q2.y == v2 && (j + 1) < c);
            r2 += (q2.z > v2) || (q2.z == v2 && (j + 2) < c);
            r2 += (q2.w > v2) || (q2.w == v2 && (j + 3) < c);
        }
        order[0][r1] = c;
        order[1][r2] = c;

        // Inclusive prefix of below flags via ballot + cross-warp smem
        const int below1 = (v1 < thr) ? 1 : 0;
        const int below2 = (v2 < thr) ? 1 : 0;
        const unsigned m1 = __ballot_sync(0xffffffffu, below1);
        const unsigned m2 = __ballot_sync(0xffffffffu, below2);
        const int lane = c & 31;
        const int warp = c >> 5;
        const unsigned lmask = 0xffffffffu >> (31 - lane);
        const int incl1 = __popc(m1 & lmask);
        const int incl2 = __popc(m2 & lmask);
        if (lane == 31) { warpcnt[0][warp] = __popc(m1); warpcnt[1][warp] = __popc(m2); }
        __syncthreads();

        int pre1 = 0, pre2 = 0;
        for (int wi = 0; wi < warp; wi++) { pre1 += warpcnt[0][wi]; pre2 += warpcnt[1][wi]; }
        const int rank1 = max(pre1 + incl1 - 1, 0);
        const int rank2 = max(pre2 + incl2 - 1, 0);

        // Scatter inverse maps (targets are distinct -> conflict-free):
        // feature1 channel c (below1) sources x2 plane order2[rank1]
        if (below1) cross[1][order[1][rank1]] = c | 512;
        // feature2 channel c (below2) sources x1 plane order1[rank2]
        if (below2) cross[0][order[0][rank2]] = c | 512;
        __syncthreads();

        // keep bit: x1 plane c kept by feature1 iff !below1; x2 by feature2 iff !below2
        g_cons[0][c] = (below1 ? 0 : 1) | (cross[0][c] << 1);
        g_cons[1][c] = (below2 ? 0 : 1) | (cross[1][c] << 1);

        __threadfence();
        __syncthreads();
        if (tid == 0) atomicExch(&g_flag, 1);
        return;
    }

    // ---------------- workers: one source plane per block ----------------
    if (tid == 0) {
        volatile int* f = &g_flag;
        if (*f == 0) { while (*f == 0) __nanosleep(40); }
        __threadfence();
    }
    __syncthreads();

    // bid-1 -> (b, t, c)
    const unsigned r = blockIdx.x - 1;
    const unsigned b = r >> 9;                 // / (2*C_)
    const unsigned t = (r >> 8) & 1;           // 0: x1 source, 1: x2 source
    const unsigned c = r & (C_ - 1);

    const int cw = g_cons[t][c];
    if (cw == 0) return;                       // plane has no consumers

    const int keep  = cw & 1;
    const int hasx  = (cw >> 10) & 1;
    const unsigned xc = (cw >> 1) & 255;       // cross channel

    const float4* __restrict__ src = t ? x2 : x1;
    const float4* sp = src + (b * C_ + c) * HW4;

    // destinations: keep -> (feature t, c); cross -> (feature 1-t, xc)
    float4* dp0 = out + ((t * B_ + b) * C_ + c) * HW4;
    float4* dp1 = out + (((1 - t) * B_ + b) * C_ + xc) * HW4;

    // Read plane once with streaming (evict-first) loads — each source byte
    // is consumed exactly once, so L2 residency has no value for reads;
    // keep L2 capacity for dirty output lines instead.
    float4 v0 = __ldcs(&sp[tid]);
    float4 v1 = __ldcs(&sp[tid + 256]);
    float4 v2 = __ldcs(&sp[tid + 512]);
    float4 v3;
    const int tail = tid < (HW4 - 768);        // 16 tail elements
    if (tail) v3 = __ldcs(&sp[tid + 768]);

    if (keep) {
        dp0[tid]       = v0;
        dp0[tid + 256] = v1;
        dp0[tid + 512] = v2;
        if (tail) dp0[tid + 768] = v3;
    }
    if (hasx) {
        dp1[tid]       = v0;
        dp1[tid + 256] = v1;
        dp1[tid + 512] = v2;
        if (tail) dp1[tid + 768] = v3;
    }
}

extern "C" void kernel_launch(void* const* d_in, const int* in_sizes, int n_in,
                              void* d_out, int out_size) {
    const float* x1  = (const float*)d_in[0];
    const float* x2  = (const float*)d_in[1];
    const float* w1  = (const float*)d_in[2];
    const float* w2  = (const float*)d_in[3];
    const float* thr = (const float*)d_in[4];

    exchange_fused<<<2 * C_ * B_ + 1, 256>>>(w1, w2, thr,
                                             (const float4*)x1,
                                             (const float4*)x2,
                                             (float4*)d_out);
}

// round 10
// speedup vs baseline: 1.1930x; 1.1930x over previous
#include <cuda_runtime.h>

// Shapes (fixed by the problem)
#define B_  32
#define C_  256
#define HW4 784                        // (56*56)/4 float4 per plane

// Consumer table, built by leader block:
// g_cons[t][c]: bit0 = keep (output (feature t, c));
//               bit10 = has cross consumer; bits[1..8] = cross channel xc.
// Persists across graph replays; leader rewrites identical values each call.
__device__ int g_cons[2][C_];
__device__ int g_flag;

// ---------------------------------------------------------------------------
// Single kernel. Block 0: build consumer table. Worker blocks: TWO source
// planes each (same tensor t, adjacent channels) — all loads issued before
// any store for deeper MLP. Default cache policy everywhere (R9 lesson).
// ---------------------------------------------------------------------------
__global__ __launch_bounds__(256)
void exchange_fused(const float* __restrict__ w1,
                    const float* __restrict__ w2,
                    const float* __restrict__ thr_p,
                    const float4* __restrict__ x1,
                    const float4* __restrict__ x2,
                    float4* __restrict__ out) {
    const int tid = threadIdx.x;

    if (blockIdx.x == 0) {
        // ---------------- leader: build consumer table ----------------
        __shared__ float a[2][C_];
        __shared__ int   order[2][C_];
        __shared__ int   warpcnt[2][8];
        __shared__ int   cross[2][C_];   // cross[t][c] = (xc|512) or 0

        const int c = tid;
        const float thr = thr_p[0];
        const float v1 = fabsf(w1[c]);
        const float v2 = fabsf(w2[c]);
        a[0][c] = v1;
        a[1][c] = v2;
        cross[0][c] = 0;
        cross[1][c] = 0;
        __syncthreads();

        // Stable descending rank (ties by ascending index), float4 smem reads
        int r1 = 0, r2 = 0;
        const float4* a1v = (const float4*)a[0];
        const float4* a2v = (const float4*)a[1];
#pragma unroll 4
        for (int j4 = 0; j4 < C_ / 4; j4++) {
            const float4 q1 = a1v[j4];
            const float4 q2 = a2v[j4];
            const int j = j4 * 4;
            r1 += (q1.x > v1) || (q1.x == v1 && (j + 0) < c);
            r1 += (q1.y > v1) || (q1.y == v1 && (j + 1) < c);
            r1 += (q1.z > v1) || (q1.z == v1 && (j + 2) < c);
            r1 += (q1.w > v1) || (q1.w == v1 && (j + 3) < c);
            r2 += (q2.x > v2) || (q2.x == v2 && (j + 0) < c);
            r2 += (q2.y > v2) || (q2.y == v2 && (j + 1) < c);
            r2 += (q2.z > v2) || (q2.z == v2 && (j + 2) < c);
            r2 += (q2.w > v2) || (q2.w == v2 && (j + 3) < c);
        }
        order[0][r1] = c;
        order[1][r2] = c;

        // Inclusive prefix of below flags via ballot + cross-warp smem
        const int below1 = (v1 < thr) ? 1 : 0;
        const int below2 = (v2 < thr) ? 1 : 0;
        const unsigned m1 = __ballot_sync(0xffffffffu, below1);
        const unsigned m2 = __ballot_sync(0xffffffffu, below2);
        const int lane = c & 31;
        const int warp = c >> 5;
        const unsigned lmask = 0xffffffffu >> (31 - lane);
        const int incl1 = __popc(m1 & lmask);
        const int incl2 = __popc(m2 & lmask);
        if (lane == 31) { warpcnt[0][warp] = __popc(m1); warpcnt[1][warp] = __popc(m2); }
        __syncthreads();

        int pre1 = 0, pre2 = 0;
        for (int wi = 0; wi < warp; wi++) { pre1 += warpcnt[0][wi]; pre2 += warpcnt[1][wi]; }
        const int rank1 = max(pre1 + incl1 - 1, 0);
        const int rank2 = max(pre2 + incl2 - 1, 0);

        // Scatter inverse maps (targets distinct -> conflict-free)
        if (below1) cross[1][order[1][rank1]] = c | 512;
        if (below2) cross[0][order[0][rank2]] = c | 512;
        __syncthreads();

        g_cons[0][c] = (below1 ? 0 : 1) | (cross[0][c] << 1);
        g_cons[1][c] = (below2 ? 0 : 1) | (cross[1][c] << 1);

        __threadfence();
        __syncthreads();
        if (tid == 0) atomicExch(&g_flag, 1);
        return;
    }

    // ---------------- workers: two source planes per block ----------------
    if (tid == 0) {
        volatile int* f = &g_flag;
        if (*f == 0) { while (*f == 0) __nanosleep(40); }
        __threadfence();
    }
    __syncthreads();

    // bid-1 -> (b, t, cpair): each block covers channels c0 = 2*cpair, c0+1
    const unsigned r  = blockIdx.x - 1;         // < B_*2*(C_/2) = 8192
    const unsigned b  = r >> 8;                 // / (2 * C_/2)
    const unsigned t  = (r >> 7) & 1;
    const unsigned c0 = (r & 127) * 2;

    const int cwA = g_cons[t][c0];
    const int cwB = g_cons[t][c0 + 1];
    if ((cwA | cwB) == 0) return;

    const float4* __restrict__ src = t ? x2 : x1;
    const float4* spA = src + (b * C_ + c0) * HW4;
    const float4* spB = spA + HW4;

    const int tail = tid < (HW4 - 768);         // 16 tail elements per plane

    // Issue ALL loads first (up to 8 outstanding LDG.128 per thread)
    float4 a0, a1, a2, a3, b0, b1, b2, b3;
    if (cwA) {
        a0 = spA[tid];
        a1 = spA[tid + 256];
        a2 = spA[tid + 512];
        if (tail) a3 = spA[tid + 768];
    }
    if (cwB) {
        b0 = spB[tid];
        b1 = spB[tid + 256];
        b2 = spB[tid + 512];
        if (tail) b3 = spB[tid + 768];
    }

    // Plane A stores
    if (cwA) {
        if (cwA & 1) {                          // keep -> (feature t, c0)
            float4* d = out + ((t * B_ + b) * C_ + c0) * HW4;
            d[tid] = a0; d[tid + 256] = a1; d[tid + 512] = a2;
            if (tail) d[tid + 768] = a3;
        }
        if (cwA & (1 << 10)) {                  // cross -> (feature 1-t, xc)
            const unsigned xc = (cwA >> 1) & 255;
            float4* d = out + (((1 - t) * B_ + b) * C_ + xc) * HW4;
            d[tid] = a0; d[tid + 256] = a1; d[tid + 512] = a2;
            if (tail) d[tid + 768] = a3;
        }
    }
    // Plane B stores
    if (cwB) {
        if (cwB & 1) {
            float4* d = out + ((t * B_ + b) * C_ + c0 + 1) * HW4;
            d[tid] = b0; d[tid + 256] = b1; d[tid + 512] = b2;
            if (tail) d[tid + 768] = b3;
        }
        if (cwB & (1 << 10)) {
            const unsigned xc = (cwB >> 1) & 255;
            float4* d = out + (((1 - t) * B_ + b) * C_ + xc) * HW4;
            d[tid] = b0; d[tid + 256] = b1; d[tid + 512] = b2;
            if (tail) d[tid + 768] = b3;
        }
    }
}

extern "C" void kernel_launch(void* const* d_in, const int* in_sizes, int n_in,
                              void* d_out, int out_size) {
    const float* x1  = (const float*)d_in[0];
    const float* x2  = (const float*)d_in[1];
    const float* w1  = (const float*)d_in[2];
    const float* w2  = (const float*)d_in[3];
    const float* thr = (const float*)d_in[4];

    exchange_fused<<<B_ * C_ + 1, 256>>>(w1, w2, thr,     // 8192 workers + leader
                                         (const float4*)x1,
                                         (const float4*)x2,
                                         (float4*)d_out);
}